// round 9
// baseline (speedup 1.0000x reference)
#include <cuda_runtime.h>
#include <cstdint>

// Masked row-wise cumsum: out[r,:] = cumsum(x[r,:] * mask[r,:])
// x: f32 [4096, 32768]; mask: 4-byte 0/1 words on the wire (byte fallback
// kept); out: f32 [4096, 32768].
//
// R8 design (1 CTA/row, 512 thr, 2048-elem chunks, 4 CTAs/SM, cp.async
// prefetch into SMEM, 1 barrier/chunk) deepened to a 3-STAGE pipeline
// (wait_group 2): two chunks of x+mask always in flight per CTA, so the
// load stream survives the scan+barrier phase. Address math strength-
// reduced to running offsets (ALU was 28.7% of issue).

#ifndef CUMSUM_N
#define CUMSUM_N 32768
#endif

#define TPB    512
#define VEC    4
#define CHUNK  (TPB * VEC)      // 2048 elements
#define NWARP  (TPB / 32)       // 16
#define STAGES 3

#define XSTAGE_B (TPB * 16)     // 8192 bytes per x stage
#define MSTAGE_B (TPB * 16)     // 8192 bytes per mask stage (word mode)

__device__ __forceinline__ unsigned smem_u32(const void* p)
{
    unsigned a;
    asm("{ .reg .u64 t; cvta.to.shared.u64 t, %1; cvt.u32.u64 %0, t; }"
        : "=r"(a) : "l"(p));
    return a;
}

__device__ __forceinline__ void cp_async16(unsigned dst, const void* src)
{
    asm volatile("cp.async.cg.shared.global [%0], [%1], 16;"
                 :: "r"(dst), "l"(src) : "memory");
}

__device__ __forceinline__ void cp_async4(unsigned dst, const void* src)
{
    asm volatile("cp.async.ca.shared.global [%0], [%1], 4;"
                 :: "r"(dst), "l"(src) : "memory");
}

__device__ __forceinline__ void cp_commit()
{
    asm volatile("cp.async.commit_group;" ::: "memory");
}

__device__ __forceinline__ void cp_wait2()
{
    asm volatile("cp.async.wait_group 2;" ::: "memory");
}

__global__ __launch_bounds__(TPB, 4)
void masked_cumsum_row_kernel(const float* __restrict__ x,
                              const void* __restrict__ mask,
                              float* __restrict__ out,
                              int n_cols)
{
    const int row  = blockIdx.x;
    const size_t base = (size_t)row * (size_t)n_cols;

    const int tid  = threadIdx.x;
    const int lane = tid & 31;
    const int wid  = tid >> 5;

    // --- per-warp mask dtype detection (deterministic, no barrier) ---
    const unsigned probe = ((const unsigned*)mask)[lane];
    const bool clean = (probe == 0u) | (probe == 1u) | (probe == 0x3F800000u);
    const bool word_mode = __all_sync(0xffffffffu, clean);

    __shared__ float4 s_x[STAGES][TPB];           // 24 KB
    __shared__ uint4  s_m[STAGES][TPB];           // 24 KB (byte mode: 2KB/stage used)
    __shared__ float  s_warp[2][NWARP];

    const unsigned sx_t  = smem_u32(&s_x[0][tid]);           // stage 0, own slice
    const unsigned sm_t  = smem_u32(&s_m[0][tid]);
    const unsigned smb_t = smem_u32(&s_m[0][0]) + tid * 4;    // byte-mode slice

    const int nch = n_cols / CHUNK;   // 16

    // running global pointers (strength-reduced)
    const float*    xg = x + base + (size_t)tid * VEC;                 // next chunk to PREFETCH
    const uint8_t*  mg_b = (const uint8_t*)mask + base + (size_t)tid * VEC;
    const unsigned* mg_w = (const unsigned*)mask + base + (size_t)tid * VEC;
    float*          og = out + base + (size_t)tid * VEC;               // next chunk to STORE

    // ---- prologue: prefetch chunks 0..2 ----
    #pragma unroll
    for (int s = 0; s < STAGES; s++) {
        cp_async16(sx_t + s * XSTAGE_B, xg);
        if (word_mode) cp_async16(sm_t + s * MSTAGE_B, mg_w);
        else           cp_async4(smb_t + s * MSTAGE_B, mg_b);
        cp_commit();
        xg   += CHUNK;
        mg_w += CHUNK;
        mg_b += CHUNK;
    }

    float carry = 0.0f;
    int p = 0;      // consume stage
    int pp = 0;     // ping-pong for warp totals

    #pragma unroll 1
    for (int c = 0; c < nch; c++) {
        cp_wait2();   // chunk c's group has drained (own slices visible)

        const float4 xv = s_x[p][tid];

        float v0, v1, v2, v3;
        if (word_mode) {
            const uint4 mv = s_m[p][tid];
            v0 = mv.x ? xv.x : 0.f;
            v1 = mv.y ? xv.y : 0.f;
            v2 = mv.z ? xv.z : 0.f;
            v3 = mv.w ? xv.w : 0.f;
        } else {
            const unsigned mv =
                *reinterpret_cast<const unsigned*>(
                    reinterpret_cast<const uint8_t*>(&s_m[p][0]) + tid * 4);
            v0 = (mv & 0x000000FFu) ? xv.x : 0.f;
            v1 = (mv & 0x0000FF00u) ? xv.y : 0.f;
            v2 = (mv & 0x00FF0000u) ? xv.z : 0.f;
            v3 = (mv & 0xFF000000u) ? xv.w : 0.f;
        }

        // ---- refill stage p with chunk c+STAGES (own slice already consumed) ----
        if (c + STAGES < nch) {
            cp_async16(sx_t + p * XSTAGE_B, xg);
            if (word_mode) cp_async16(sm_t + p * MSTAGE_B, mg_w);
            else           cp_async4(smb_t + p * MSTAGE_B, mg_b);
            xg   += CHUNK;
            mg_w += CHUNK;
            mg_b += CHUNK;
        }
        cp_commit();   // uniform group accounting

        // ---- thread-local inclusive scan of 4 ----
        const float s0 = v0;
        const float s1 = s0 + v1;
        const float s2 = s1 + v2;
        const float s3 = s2 + v3;

        // ---- warp inclusive scan of per-thread totals ----
        float t = s3;
        #pragma unroll
        for (int d = 1; d < 32; d <<= 1) {
            float nv = __shfl_up_sync(0xffffffffu, t, d);
            if (lane >= d) t += nv;
        }
        const float thread_excl = t - s3;

        if (lane == 31) s_warp[pp][wid] = t;
        __syncthreads();                      // the ONLY barrier per chunk

        // ---- every warp redundantly scans the 16 warp totals ----
        float wincl = (lane < NWARP) ? s_warp[pp][lane] : 0.f;
        #pragma unroll
        for (int d = 1; d < NWARP; d <<= 1) {
            float nv = __shfl_up_sync(0xffffffffu, wincl, d);
            if (lane >= d) wincl += nv;
        }
        const float warp_excl = (wid == 0)
            ? 0.f
            : __shfl_sync(0xffffffffu, wincl, wid - 1);
        const float block_tot = __shfl_sync(0xffffffffu, wincl, NWARP - 1);

        const float offv = carry + warp_excl + thread_excl;

        float4 o;
        o.x = s0 + offv;
        o.y = s1 + offv;
        o.z = s2 + offv;
        o.w = s3 + offv;
        __stcs(reinterpret_cast<float4*>(og), o);
        og += CHUNK;

        carry += block_tot;
        p = (p == STAGES - 1) ? 0 : p + 1;
        pp ^= 1;
    }
}

extern "C" void kernel_launch(void* const* d_in, const int* in_sizes, int n_in,
                              void* d_out, int out_size)
{
    const float* x    = (const float*)d_in[0];
    const void*  mask = d_in[1];
    float*       out  = (float*)d_out;

    const int n_cols = CUMSUM_N;
    const int n_rows = in_sizes[0] / n_cols;   // 4096

    masked_cumsum_row_kernel<<<n_rows, TPB>>>(x, mask, out, n_cols);
}